// round 14
// baseline (speedup 1.0000x reference)
#include <cuda_runtime.h>

// out4[((b*H+y)*W+x)*768 + ch*4 + i] = float4{ in[b,ch,y+i-3, x-2..x+1] },
// zero-padded; lanes z,w zeroed when i==3. B=8, C=192, H=W=48.
// Block = (b, y, 12-wide x-tile, 48-channel quarter); 384 threads.
// TWO threads per chi: half 0 -> xl 0..5 (window w[0..8]),
//                      half 1 -> xl 6..11 (window w[6..14]).

#define B_     8
#define C_     192
#define H_     48
#define W_     48
#define TX     12
#define XT     (W_ / TX)            // 4 x-tiles
#define CSPL   4                    // channel splits per position
#define CH     (C_ / CSPL)          // 48 channels per block
#define ROWS   (CH * 4)             // 192 chi rows per block
#define PITCH  15                   // cols x0-2 .. x0+12 ; gcd(15,32)=1
#define SELEMS (ROWS * PITCH)       // 2880 floats = 11520 B
#define NTHR   384

__global__ void __launch_bounds__(NTHR)
block_sample_smem(const float* __restrict__ in, float4* __restrict__ out)
{
    __shared__ float s[SELEMS];

    const int tid = threadIdx.x;
    int bid = blockIdx.x;
    const int cs = bid & 3;   bid >>= 2;        // channel quarter
    const int xt = bid % XT;  bid /= XT;
    const int y  = bid % H_;
    const int b  = bid / H_;
    const int x0 = xt * TX;
    const int ch0 = cs * CH;

    // ---- load: rows y-3..y, cols x0-2..x0+12, channels ch0..ch0+47 ----
    #pragma unroll
    for (int k = 0; k < 8; k++) {               // 2880 = 7.5 * 384
        const int idx = k * NTHR + tid;
        if (k == 7 && idx >= SELEMS) break;
        const int sc  = idx % PITCH;       // 0..14
        const int rf  = idx / PITCH;       // ch_local*4 + r
        const int gy  = y + (rf & 3) - 3;  // <= 47 always
        const int gx  = x0 - 2 + sc;       // -2 .. 48
        float v = 0.f;
        if (gy >= 0 && gx >= 0 && gx < W_)
            v = __ldg(in + ((b * C_ + ch0 + (rf >> 2)) * H_ + gy) * W_ + gx);
        s[idx] = v;
    }
    __syncthreads();

    // ---- store: 2 threads per chi; each reads a 9-word window (conflict-free
    //      scalar LDS) and emits 6 coalesced streaming STG.128 ----
    const int chi  = tid % ROWS;                 // ch_local*4 + i
    const int half = tid / ROWS;                 // 0 -> xl 0..5, 1 -> xl 6..11
    const bool msk = (chi & 3) == 3;             // i == 3 -> mask z,w
    const int base = half * 6;                   // window word offset & xl offset
    const float* row = &s[chi * PITCH + base];

    float w[9];
    #pragma unroll
    for (int c = 0; c < 9; c++) w[c] = row[c];

    float4* o = out + (long)((b * H_ + y) * W_ + x0 + base) * (C_ * 4) + ch0 * 4 + chi;
    #pragma unroll
    for (int xl = 0; xl < 6; xl++) {
        __stcs(o + xl * (C_ * 4),
               make_float4(w[xl],
                           w[xl + 1],
                           msk ? 0.f : w[xl + 2],
                           msk ? 0.f : w[xl + 3]));
    }
}

extern "C" void kernel_launch(void* const* d_in, const int* in_sizes, int n_in,
                              void* d_out, int out_size)
{
    const float* in  = (const float*)d_in[0];
    float4*      out = (float4*)d_out;

    const int blocks = B_ * H_ * XT * CSPL;   // 6144
    block_sample_smem<<<blocks, NTHR>>>(in, out);
}